// round 1
// baseline (speedup 1.0000x reference)
#include <cuda_runtime.h>
#include <math.h>

#define DIMX 256
#define NB   32
#define BMROWS 8192
#define LN_EPS 1e-5f
#define ATT_SCALE 0.17677669529663687f   // 32^-0.5

// ---------------- scratch (static device globals; no allocation) ----------------
__device__ float g_qW  [(size_t)BMROWS * 2048];  // q folded through Wk, per head: [row][h*256+c]
__device__ float g_qkb [BMROWS * 8];             // q . bk per head
__device__ float g_ybar[(size_t)BMROWS * 2048];  // attn-weighted LNv(y) rows: [row][h*256+c]
__device__ float g_t   [(size_t)BMROWS * DIMX];  // pre-FFN LayerNorm output (residual branch)

__device__ __forceinline__ float warp_sum(float v) {
#pragma unroll
    for (int o = 16; o; o >>= 1) v += __shfl_xor_sync(0xffffffffu, v, o);
    return v;
}

// =============================================================================
// Kernel A: q = LN(x)@Wq^T + bq ; qW[h,c] = sum_d q[h*32+d]*Wk[h*32+d,c] ;
//           qkb[h] = sum_d q[h*32+d]*bk[h*32+d]
// One CTA = 16 rows, 256 threads.
// =============================================================================
__global__ __launch_bounds__(256) void kA(
    const float* __restrict__ x,
    const float* __restrict__ lnq_w, const float* __restrict__ lnq_b,
    const float* __restrict__ Wq, const float* __restrict__ bq,
    const float* __restrict__ Wk, const float* __restrict__ bk)
{
    __shared__ float xs[16][DIMX];
    __shared__ float qs[16][DIMX];
    const int tid = threadIdx.x, lane = tid & 31, w = tid >> 5;
    const int row0 = blockIdx.x * 16;

    // ---- load + LayerNorm(x) (warp per 2 rows) ----
#pragma unroll
    for (int rr = 0; rr < 2; rr++) {
        int r = w * 2 + rr;
        const float* xr = x + (size_t)(row0 + r) * DIMX;
        float v[8]; float s = 0.f;
#pragma unroll
        for (int i = 0; i < 8; i++) { v[i] = xr[lane + 32 * i]; s += v[i]; }
        s = warp_sum(s);
        float mu = s * (1.f / DIMX);
        float sv = 0.f;
#pragma unroll
        for (int i = 0; i < 8; i++) { float d = v[i] - mu; sv += d * d; }
        sv = warp_sum(sv);
        float rs = rsqrtf(sv * (1.f / DIMX) + LN_EPS);
#pragma unroll
        for (int i = 0; i < 8; i++) {
            int c = lane + 32 * i;
            xs[r][c] = (v[i] - mu) * rs * lnq_w[c] + lnq_b[c];
        }
    }
    __syncthreads();

    // ---- q rows: thread = output column o = tid ----
    {
        float acc[16];
#pragma unroll
        for (int r = 0; r < 16; r++) acc[r] = 0.f;
        const float4* wr = (const float4*)(Wq + (size_t)tid * DIMX);
        for (int c4 = 0; c4 < 64; c4++) {
            float4 w4 = wr[c4];
#pragma unroll
            for (int r = 0; r < 16; r++) {
                float4 x4 = *(const float4*)&xs[r][c4 * 4];
                acc[r] = fmaf(x4.x, w4.x, acc[r]);
                acc[r] = fmaf(x4.y, w4.y, acc[r]);
                acc[r] = fmaf(x4.z, w4.z, acc[r]);
                acc[r] = fmaf(x4.w, w4.w, acc[r]);
            }
        }
        float bb = bq[tid];
#pragma unroll
        for (int r = 0; r < 16; r++) qs[r][tid] = acc[r] + bb;
    }
    __syncthreads();

    // ---- qkb (tiny) ----
    if (tid < 128) {
        int r = tid >> 3, h = tid & 7;
        float s = 0.f;
#pragma unroll
        for (int d = 0; d < 32; d++) s += qs[r][h * 32 + d] * bk[h * 32 + d];
        g_qkb[(row0 + r) * 8 + h] = s;
    }

    // ---- qW: thread = column c = tid, loop heads ----
    for (int h = 0; h < 8; h++) {
        float acc[16];
#pragma unroll
        for (int r = 0; r < 16; r++) acc[r] = 0.f;
#pragma unroll
        for (int d4 = 0; d4 < 8; d4++) {
            float wv0 = Wk[(size_t)(h * 32 + d4 * 4 + 0) * DIMX + tid];
            float wv1 = Wk[(size_t)(h * 32 + d4 * 4 + 1) * DIMX + tid];
            float wv2 = Wk[(size_t)(h * 32 + d4 * 4 + 2) * DIMX + tid];
            float wv3 = Wk[(size_t)(h * 32 + d4 * 4 + 3) * DIMX + tid];
#pragma unroll
            for (int r = 0; r < 16; r++) {
                float4 q4 = *(const float4*)&qs[r][h * 32 + d4 * 4];
                acc[r] = fmaf(q4.x, wv0, acc[r]);
                acc[r] = fmaf(q4.y, wv1, acc[r]);
                acc[r] = fmaf(q4.z, wv2, acc[r]);
                acc[r] = fmaf(q4.w, wv3, acc[r]);
            }
        }
#pragma unroll
        for (int r = 0; r < 16; r++)
            g_qW[(size_t)(row0 + r) * 2048 + h * 256 + tid] = acc[r];
    }
}

// =============================================================================
// Kernel B: per (b,m): LN(y rows), logits via qW, softmax over N, ybar.
// One CTA per row (8192 CTAs), 256 threads. Only kernel touching y (256 MB).
// =============================================================================
__global__ __launch_bounds__(256) void kB(
    const float* __restrict__ y,
    const float* __restrict__ lnk_w, const float* __restrict__ lnk_b,
    const float* __restrict__ lnv_w, const float* __restrict__ lnv_b)
{
    __shared__ float ysn[32][260];   // normalized y rows (padded vs bank conflicts)
    __shared__ float qWk[8][260];    // qW * lnk_w
    __shared__ float la[8][33];      // logits
    __shared__ float attn[8][33];
    __shared__ float qb2[8];

    const int tid = threadIdx.x, lane = tid & 31, w = tid >> 5;
    const int bm = blockIdx.x;
    const float4* ybase = (const float4*)(y + (size_t)bm * (NB * DIMX));

    // ---- cooperative load of the 32x256 tile ----
#pragma unroll
    for (int j = 0; j < 8; j++) {
        int fi = j * 256 + tid;          // float4 index 0..2047
        int n = fi >> 6, c4 = fi & 63;
        float4 v = ybase[fi];
        *(float4*)&ysn[n][c4 * 4] = v;
    }
    if (tid < 8) qb2[tid] = g_qkb[bm * 8 + tid];
    __syncthreads();

    // ---- LayerNorm each of the 32 rows (pure normalization; affines folded later) ----
#pragma unroll
    for (int rr = 0; rr < 4; rr++) {
        int n = w * 4 + rr;
        float v[8]; float s = 0.f;
#pragma unroll
        for (int i = 0; i < 8; i++) { v[i] = ysn[n][lane + 32 * i]; s += v[i]; }
        s = warp_sum(s);
        float mu = s * (1.f / DIMX);
        float sv = 0.f;
#pragma unroll
        for (int i = 0; i < 8; i++) { float d = v[i] - mu; sv += d * d; }
        sv = warp_sum(sv);
        float rs = rsqrtf(sv * (1.f / DIMX) + LN_EPS);
#pragma unroll
        for (int i = 0; i < 8; i++) ysn[n][lane + 32 * i] = (v[i] - mu) * rs;
    }

    // ---- fold lnk affine into qW; accumulate bias term into qb2 ----
    {
        float lw = lnk_w[tid], lb = lnk_b[tid];
        const float* qWrow = g_qW + (size_t)bm * 2048;
#pragma unroll
        for (int h = 0; h < 8; h++) {
            float qv = qWrow[h * 256 + tid];
            qWk[h][tid] = qv * lw;
            float bp = warp_sum(qv * lb);
            if (lane == 0) atomicAdd(&qb2[h], bp);
        }
    }
    __syncthreads();

    // ---- logits: thread -> (n = tid>>3, h = tid&7) ----
    {
        int n = tid >> 3, h = tid & 7;
        float s = 0.f;
        for (int c4 = 0; c4 < 64; c4++) {
            float4 a4 = *(const float4*)&ysn[n][c4 * 4];
            float4 b4 = *(const float4*)&qWk[h][c4 * 4];
            s += a4.x * b4.x + a4.y * b4.y + a4.z * b4.z + a4.w * b4.w;
        }
        la[h][n] = (s + qb2[h]) * ATT_SCALE;
    }
    __syncthreads();

    // ---- softmax over N per head (warp = head) ----
    {
        float v = la[w][lane];
        float mx = v;
#pragma unroll
        for (int o = 16; o; o >>= 1) mx = fmaxf(mx, __shfl_xor_sync(0xffffffffu, mx, o));
        float e = __expf(v - mx);
        float s = warp_sum(e);
        attn[w][lane] = e / s;
    }
    __syncthreads();

    // ---- ybar[h,c] = sum_n attn * ysn, with lnv affine folded ----
    {
        float lvw = lnv_w[tid], lvb = lnv_b[tid];
        float* outrow = g_ybar + (size_t)bm * 2048;
#pragma unroll
        for (int h = 0; h < 8; h++) {
            float acc = 0.f;
#pragma unroll
            for (int n = 0; n < 32; n++) acc = fmaf(attn[h][n], ysn[n][tid], acc);
            outrow[h * 256 + tid] = acc * lvw + lvb;
        }
    }
}

// =============================================================================
// Kernel C1: a[hd] = sum_c ybar[h,c]*Wv[hd,c] + bv ; z = a@Wp^T + bp ; t = LN(z)
// One CTA = 16 rows, 256 threads.
// =============================================================================
__global__ __launch_bounds__(256) void kC1(
    const float* __restrict__ Wv, const float* __restrict__ bv,
    const float* __restrict__ Wp, const float* __restrict__ bp,
    const float* __restrict__ pre_w, const float* __restrict__ pre_b)
{
    __shared__ float aS[16][DIMX];
    __shared__ float zS[16][DIMX];
    const int tid = threadIdx.x, lane = tid & 31, w = tid >> 5;
    const int row0 = blockIdx.x * 16;

    // ---- a: thread = output hd = tid ----
    {
        float acc[16];
#pragma unroll
        for (int r = 0; r < 16; r++) acc[r] = 0.f;
        const float4* wr = (const float4*)(Wv + (size_t)tid * DIMX);
        const int h = tid >> 5;
        for (int c4 = 0; c4 < 64; c4++) {
            float4 w4 = wr[c4];
#pragma unroll
            for (int r = 0; r < 16; r++) {
                float4 y4 = *((const float4*)(g_ybar + (size_t)(row0 + r) * 2048 + h * 256) + c4);
                acc[r] = fmaf(y4.x, w4.x, acc[r]);
                acc[r] = fmaf(y4.y, w4.y, acc[r]);
                acc[r] = fmaf(y4.z, w4.z, acc[r]);
                acc[r] = fmaf(y4.w, w4.w, acc[r]);
            }
        }
        float bb = bv[tid];
#pragma unroll
        for (int r = 0; r < 16; r++) aS[r][tid] = acc[r] + bb;
    }
    __syncthreads();

    // ---- z = a @ Wp^T + bp ----
    {
        float acc[16];
#pragma unroll
        for (int r = 0; r < 16; r++) acc[r] = 0.f;
        const float4* wr = (const float4*)(Wp + (size_t)tid * DIMX);
        for (int c4 = 0; c4 < 64; c4++) {
            float4 w4 = wr[c4];
#pragma unroll
            for (int r = 0; r < 16; r++) {
                float4 a4 = *(const float4*)&aS[r][c4 * 4];
                acc[r] = fmaf(a4.x, w4.x, acc[r]);
                acc[r] = fmaf(a4.y, w4.y, acc[r]);
                acc[r] = fmaf(a4.z, w4.z, acc[r]);
                acc[r] = fmaf(a4.w, w4.w, acc[r]);
            }
        }
        float bb = bp[tid];
#pragma unroll
        for (int r = 0; r < 16; r++) zS[r][tid] = acc[r] + bb;
    }
    __syncthreads();

    // ---- t = LN(z)*pre_w + pre_b -> g_t ----
#pragma unroll
    for (int rr = 0; rr < 2; rr++) {
        int r = w * 2 + rr;
        float v[8]; float s = 0.f;
#pragma unroll
        for (int i = 0; i < 8; i++) { v[i] = zS[r][lane + 32 * i]; s += v[i]; }
        s = warp_sum(s);
        float mu = s * (1.f / DIMX);
        float sv = 0.f;
#pragma unroll
        for (int i = 0; i < 8; i++) { float d = v[i] - mu; sv += d * d; }
        sv = warp_sum(sv);
        float rs = rsqrtf(sv * (1.f / DIMX) + LN_EPS);
#pragma unroll
        for (int i = 0; i < 8; i++) {
            int c = lane + 32 * i;
            g_t[(size_t)(row0 + r) * DIMX + c] = (v[i] - mu) * rs * pre_w[c] + pre_b[c];
        }
    }
}

// =============================================================================
// Kernel C2: h1 = gelu(t@W1^T+b1); z2 = t + h1@W2^T + b2; out = LN(z2)
// One CTA = 16 rows, 256 threads.
// =============================================================================
__global__ __launch_bounds__(256) void kC2(
    const float* __restrict__ W1, const float* __restrict__ b1,
    const float* __restrict__ W2, const float* __restrict__ b2,
    const float* __restrict__ post_w, const float* __restrict__ post_b,
    float* __restrict__ out)
{
    __shared__ float h1S[16][512];   // 32 KB; first 16 KB reused as z2 buffer afterwards
    const int tid = threadIdx.x, lane = tid & 31, w = tid >> 5;
    const int row0 = blockIdx.x * 16;

    // ---- h1 = gelu(W1 t + b1): thread handles outputs tid and tid+256 ----
#pragma unroll
    for (int oi = 0; oi < 2; oi++) {
        int o = oi * 256 + tid;
        float acc[16];
#pragma unroll
        for (int r = 0; r < 16; r++) acc[r] = 0.f;
        const float4* wr = (const float4*)(W1 + (size_t)o * DIMX);
        for (int c4 = 0; c4 < 64; c4++) {
            float4 w4 = wr[c4];
#pragma unroll
            for (int r = 0; r < 16; r++) {
                float4 t4 = *((const float4*)(g_t + (size_t)(row0 + r) * DIMX) + c4);
                acc[r] = fmaf(t4.x, w4.x, acc[r]);
                acc[r] = fmaf(t4.y, w4.y, acc[r]);
                acc[r] = fmaf(t4.z, w4.z, acc[r]);
                acc[r] = fmaf(t4.w, w4.w, acc[r]);
            }
        }
        float bb = b1[o];
#pragma unroll
        for (int r = 0; r < 16; r++) {
            float zv = acc[r] + bb;
            h1S[r][o] = 0.5f * zv * (1.0f + erff(zv * 0.7071067811865475f));
        }
    }
    __syncthreads();

    // ---- h2 + residual, kept in registers ----
    float z2[16];
    {
        float acc[16];
#pragma unroll
        for (int r = 0; r < 16; r++) acc[r] = 0.f;
        const float4* wr = (const float4*)(W2 + (size_t)tid * 512);
        for (int c4 = 0; c4 < 128; c4++) {
            float4 w4 = wr[c4];
#pragma unroll
            for (int r = 0; r < 16; r++) {
                float4 hh = *(const float4*)&h1S[r][c4 * 4];
                acc[r] = fmaf(hh.x, w4.x, acc[r]);
                acc[r] = fmaf(hh.y, w4.y, acc[r]);
                acc[r] = fmaf(hh.z, w4.z, acc[r]);
                acc[r] = fmaf(hh.w, w4.w, acc[r]);
            }
        }
        float bb = b2[tid];
#pragma unroll
        for (int r = 0; r < 16; r++)
            z2[r] = g_t[(size_t)(row0 + r) * DIMX + tid] + acc[r] + bb;
    }
    __syncthreads();

    // ---- stash z2 into the (now free) h1S region for the row-wise LN ----
    float* z2S = &h1S[0][0];   // treated as [16][256]
#pragma unroll
    for (int r = 0; r < 16; r++) z2S[r * 256 + tid] = z2[r];
    __syncthreads();

    // ---- final LN -> out ----
#pragma unroll
    for (int rr = 0; rr < 2; rr++) {
        int r = w * 2 + rr;
        float v[8]; float s = 0.f;
#pragma unroll
        for (int i = 0; i < 8; i++) { v[i] = z2S[r * 256 + lane + 32 * i]; s += v[i]; }
        s = warp_sum(s);
        float mu = s * (1.f / DIMX);
        float sv = 0.f;
#pragma unroll
        for (int i = 0; i < 8; i++) { float d = v[i] - mu; sv += d * d; }
        sv = warp_sum(sv);
        float rs = rsqrtf(sv * (1.f / DIMX) + LN_EPS);
#pragma unroll
        for (int i = 0; i < 8; i++) {
            int c = lane + 32 * i;
            out[(size_t)(row0 + r) * DIMX + c] = (v[i] - mu) * rs * post_w[c] + post_b[c];
        }
    }
}

// =============================================================================
extern "C" void kernel_launch(void* const* d_in, const int* in_sizes, int n_in,
                              void* d_out, int out_size)
{
    const float* x      = (const float*)d_in[0];
    const float* y      = (const float*)d_in[1];
    const float* lnq_w  = (const float*)d_in[2];
    const float* lnq_b  = (const float*)d_in[3];
    const float* Wq     = (const float*)d_in[4];
    const float* bq     = (const float*)d_in[5];
    const float* lnk_w  = (const float*)d_in[6];
    const float* lnk_b  = (const float*)d_in[7];
    const float* Wk     = (const float*)d_in[8];
    const float* bk     = (const float*)d_in[9];
    const float* lnv_w  = (const float*)d_in[10];
    const float* lnv_b  = (const float*)d_in[11];
    const float* Wv     = (const float*)d_in[12];
    const float* bv     = (const float*)d_in[13];
    const float* Wp     = (const float*)d_in[14];
    const float* bp     = (const float*)d_in[15];
    const float* pre_w  = (const float*)d_in[16];
    const float* pre_b  = (const float*)d_in[17];
    const float* W1     = (const float*)d_in[18];
    const float* b1     = (const float*)d_in[19];
    const float* W2     = (const float*)d_in[20];
    const float* b2     = (const float*)d_in[21];
    const float* post_w = (const float*)d_in[22];
    const float* post_b = (const float*)d_in[23];
    float* out = (float*)d_out;

    kA <<<BMROWS / 16, 256>>> (x, lnq_w, lnq_b, Wq, bq, Wk, bk);
    kB <<<BMROWS,      256>>> (y, lnk_w, lnk_b, lnv_w, lnv_b);
    kC1<<<BMROWS / 16, 256>>> (Wv, bv, Wp, bp, pre_w, pre_b);
    kC2<<<BMROWS / 16, 256>>> (W1, b1, W2, b2, post_w, post_b, out);
}

// round 2
// speedup vs baseline: 1.0007x; 1.0007x over previous
#include <cuda_runtime.h>
#include <math.h>

#define DIMX 256
#define NB   32
#define BMROWS 8192
#define LN_EPS 1e-5f
#define ATT_SCALE 0.17677669529663687f   // 32^-0.5

// ---------------- scratch (static device globals; no allocation) ----------------
__device__ float g_qW  [(size_t)BMROWS * 2048];  // q folded through Wk, per head: [row][h*256+c]
__device__ float g_qkb [BMROWS * 8];             // q . bk per head
__device__ float g_ybar[(size_t)BMROWS * 2048];  // attn-weighted LNv(y) rows: [row][h*256+c]
__device__ float g_t   [(size_t)BMROWS * DIMX];  // pre-FFN LayerNorm output (residual branch)

__device__ __forceinline__ float warp_sum(float v) {
#pragma unroll
    for (int o = 16; o; o >>= 1) v += __shfl_xor_sync(0xffffffffu, v, o);
    return v;
}

// =============================================================================
// Kernel A: q = LN(x)@Wq^T + bq ; qW[h,c] = sum_d q[h*32+d]*Wk[h*32+d,c] ;
//           qkb[h] = sum_d q[h*32+d]*bk[h*32+d]
// One CTA = 16 rows, 256 threads.
// =============================================================================
__global__ __launch_bounds__(256) void kA(
    const float* __restrict__ x,
    const float* __restrict__ lnq_w, const float* __restrict__ lnq_b,
    const float* __restrict__ Wq, const float* __restrict__ bq,
    const float* __restrict__ Wk, const float* __restrict__ bk)
{
    __shared__ float xs[16][DIMX];
    __shared__ float qs[16][DIMX];
    const int tid = threadIdx.x, lane = tid & 31, w = tid >> 5;
    const int row0 = blockIdx.x * 16;

    // ---- load + LayerNorm(x) (warp per 2 rows) ----
#pragma unroll
    for (int rr = 0; rr < 2; rr++) {
        int r = w * 2 + rr;
        const float* xr = x + (size_t)(row0 + r) * DIMX;
        float v[8]; float s = 0.f;
#pragma unroll
        for (int i = 0; i < 8; i++) { v[i] = xr[lane + 32 * i]; s += v[i]; }
        s = warp_sum(s);
        float mu = s * (1.f / DIMX);
        float sv = 0.f;
#pragma unroll
        for (int i = 0; i < 8; i++) { float d = v[i] - mu; sv += d * d; }
        sv = warp_sum(sv);
        float rs = rsqrtf(sv * (1.f / DIMX) + LN_EPS);
#pragma unroll
        for (int i = 0; i < 8; i++) {
            int c = lane + 32 * i;
            xs[r][c] = (v[i] - mu) * rs * lnq_w[c] + lnq_b[c];
        }
    }
    __syncthreads();

    // ---- q rows: thread = output column o = tid ----
    {
        float acc[16];
#pragma unroll
        for (int r = 0; r < 16; r++) acc[r] = 0.f;
        const float4* wr = (const float4*)(Wq + (size_t)tid * DIMX);
        for (int c4 = 0; c4 < 64; c4++) {
            float4 w4 = wr[c4];
#pragma unroll
            for (int r = 0; r < 16; r++) {
                float4 x4 = *(const float4*)&xs[r][c4 * 4];
                acc[r] = fmaf(x4.x, w4.x, acc[r]);
                acc[r] = fmaf(x4.y, w4.y, acc[r]);
                acc[r] = fmaf(x4.z, w4.z, acc[r]);
                acc[r] = fmaf(x4.w, w4.w, acc[r]);
            }
        }
        float bb = bq[tid];
#pragma unroll
        for (int r = 0; r < 16; r++) qs[r][tid] = acc[r] + bb;
    }
    __syncthreads();

    // ---- qkb (tiny) ----
    if (tid < 128) {
        int r = tid >> 3, h = tid & 7;
        float s = 0.f;
#pragma unroll
        for (int d = 0; d < 32; d++) s += qs[r][h * 32 + d] * bk[h * 32 + d];
        g_qkb[(row0 + r) * 8 + h] = s;
    }

    // ---- qW: thread = column c = tid, loop heads ----
    for (int h = 0; h < 8; h++) {
        float acc[16];
#pragma unroll
        for (int r = 0; r < 16; r++) acc[r] = 0.f;
#pragma unroll
        for (int d4 = 0; d4 < 8; d4++) {
            float wv0 = Wk[(size_t)(h * 32 + d4 * 4 + 0) * DIMX + tid];
            float wv1 = Wk[(size_t)(h * 32 + d4 * 4 + 1) * DIMX + tid];
            float wv2 = Wk[(size_t)(h * 32 + d4 * 4 + 2) * DIMX + tid];
            float wv3 = Wk[(size_t)(h * 32 + d4 * 4 + 3) * DIMX + tid];
#pragma unroll
            for (int r = 0; r < 16; r++) {
                float4 q4 = *(const float4*)&qs[r][h * 32 + d4 * 4];
                acc[r] = fmaf(q4.x, wv0, acc[r]);
                acc[r] = fmaf(q4.y, wv1, acc[r]);
                acc[r] = fmaf(q4.z, wv2, acc[r]);
                acc[r] = fmaf(q4.w, wv3, acc[r]);
            }
        }
#pragma unroll
        for (int r = 0; r < 16; r++)
            g_qW[(size_t)(row0 + r) * 2048 + h * 256 + tid] = acc[r];
    }
}

// =============================================================================
// Kernel B: per (b,m): LN(y rows), logits via qW, softmax over N, ybar.
// One CTA per row (8192 CTAs), 256 threads. Only kernel touching y (256 MB).
// =============================================================================
__global__ __launch_bounds__(256) void kB(
    const float* __restrict__ y,
    const float* __restrict__ lnk_w, const float* __restrict__ lnk_b,
    const float* __restrict__ lnv_w, const float* __restrict__ lnv_b)
{
    __shared__ float ysn[32][260];   // normalized y rows (padded vs bank conflicts)
    __shared__ float qWk[8][260];    // qW * lnk_w
    __shared__ float la[8][33];      // logits
    __shared__ float attn[8][33];
    __shared__ float qb2[8];

    const int tid = threadIdx.x, lane = tid & 31, w = tid >> 5;
    const int bm = blockIdx.x;
    const float4* ybase = (const float4*)(y + (size_t)bm * (NB * DIMX));

    // ---- cooperative load of the 32x256 tile ----
#pragma unroll
    for (int j = 0; j < 8; j++) {
        int fi = j * 256 + tid;          // float4 index 0..2047
        int n = fi >> 6, c4 = fi & 63;
        float4 v = ybase[fi];
        *(float4*)&ysn[n][c4 * 4] = v;
    }
    if (tid < 8) qb2[tid] = g_qkb[bm * 8 + tid];
    __syncthreads();

    // ---- LayerNorm each of the 32 rows (pure normalization; affines folded later) ----
#pragma unroll
    for (int rr = 0; rr < 4; rr++) {
        int n = w * 4 + rr;
        float v[8]; float s = 0.f;
#pragma unroll
        for (int i = 0; i < 8; i++) { v[i] = ysn[n][lane + 32 * i]; s += v[i]; }
        s = warp_sum(s);
        float mu = s * (1.f / DIMX);
        float sv = 0.f;
#pragma unroll
        for (int i = 0; i < 8; i++) { float d = v[i] - mu; sv += d * d; }
        sv = warp_sum(sv);
        float rs = rsqrtf(sv * (1.f / DIMX) + LN_EPS);
#pragma unroll
        for (int i = 0; i < 8; i++) ysn[n][lane + 32 * i] = (v[i] - mu) * rs;
    }

    // ---- fold lnk affine into qW; accumulate bias term into qb2 ----
    {
        float lw = lnk_w[tid], lb = lnk_b[tid];
        const float* qWrow = g_qW + (size_t)bm * 2048;
#pragma unroll
        for (int h = 0; h < 8; h++) {
            float qv = qWrow[h * 256 + tid];
            qWk[h][tid] = qv * lw;
            float bp = warp_sum(qv * lb);
            if (lane == 0) atomicAdd(&qb2[h], bp);
        }
    }
    __syncthreads();

    // ---- logits: thread -> (n = tid>>3, h = tid&7) ----
    {
        int n = tid >> 3, h = tid & 7;
        float s = 0.f;
        for (int c4 = 0; c4 < 64; c4++) {
            float4 a4 = *(const float4*)&ysn[n][c4 * 4];
            float4 b4 = *(const float4*)&qWk[h][c4 * 4];
            s += a4.x * b4.x + a4.y * b4.y + a4.z * b4.z + a4.w * b4.w;
        }
        la[h][n] = (s + qb2[h]) * ATT_SCALE;
    }
    __syncthreads();

    // ---- softmax over N per head (warp = head) ----
    {
        float v = la[w][lane];
        float mx = v;
#pragma unroll
        for (int o = 16; o; o >>= 1) mx = fmaxf(mx, __shfl_xor_sync(0xffffffffu, mx, o));
        float e = __expf(v - mx);
        float s = warp_sum(e);
        attn[w][lane] = e / s;
    }
    __syncthreads();

    // ---- ybar[h,c] = sum_n attn * ysn, with lnv affine folded ----
    {
        float lvw = lnv_w[tid], lvb = lnv_b[tid];
        float* outrow = g_ybar + (size_t)bm * 2048;
#pragma unroll
        for (int h = 0; h < 8; h++) {
            float acc = 0.f;
#pragma unroll
            for (int n = 0; n < 32; n++) acc = fmaf(attn[h][n], ysn[n][tid], acc);
            outrow[h * 256 + tid] = acc * lvw + lvb;
        }
    }
}

// =============================================================================
// Kernel C1: a[hd] = sum_c ybar[h,c]*Wv[hd,c] + bv ; z = a@Wp^T + bp ; t = LN(z)
// One CTA = 16 rows, 256 threads.
// =============================================================================
__global__ __launch_bounds__(256) void kC1(
    const float* __restrict__ Wv, const float* __restrict__ bv,
    const float* __restrict__ Wp, const float* __restrict__ bp,
    const float* __restrict__ pre_w, const float* __restrict__ pre_b)
{
    __shared__ float aS[16][DIMX];
    __shared__ float zS[16][DIMX];
    const int tid = threadIdx.x, lane = tid & 31, w = tid >> 5;
    const int row0 = blockIdx.x * 16;

    // ---- a: thread = output hd = tid ----
    {
        float acc[16];
#pragma unroll
        for (int r = 0; r < 16; r++) acc[r] = 0.f;
        const float4* wr = (const float4*)(Wv + (size_t)tid * DIMX);
        const int h = tid >> 5;
        for (int c4 = 0; c4 < 64; c4++) {
            float4 w4 = wr[c4];
#pragma unroll
            for (int r = 0; r < 16; r++) {
                float4 y4 = *((const float4*)(g_ybar + (size_t)(row0 + r) * 2048 + h * 256) + c4);
                acc[r] = fmaf(y4.x, w4.x, acc[r]);
                acc[r] = fmaf(y4.y, w4.y, acc[r]);
                acc[r] = fmaf(y4.z, w4.z, acc[r]);
                acc[r] = fmaf(y4.w, w4.w, acc[r]);
            }
        }
        float bb = bv[tid];
#pragma unroll
        for (int r = 0; r < 16; r++) aS[r][tid] = acc[r] + bb;
    }
    __syncthreads();

    // ---- z = a @ Wp^T + bp ----
    {
        float acc[16];
#pragma unroll
        for (int r = 0; r < 16; r++) acc[r] = 0.f;
        const float4* wr = (const float4*)(Wp + (size_t)tid * DIMX);
        for (int c4 = 0; c4 < 64; c4++) {
            float4 w4 = wr[c4];
#pragma unroll
            for (int r = 0; r < 16; r++) {
                float4 a4 = *(const float4*)&aS[r][c4 * 4];
                acc[r] = fmaf(a4.x, w4.x, acc[r]);
                acc[r] = fmaf(a4.y, w4.y, acc[r]);
                acc[r] = fmaf(a4.z, w4.z, acc[r]);
                acc[r] = fmaf(a4.w, w4.w, acc[r]);
            }
        }
        float bb = bp[tid];
#pragma unroll
        for (int r = 0; r < 16; r++) zS[r][tid] = acc[r] + bb;
    }
    __syncthreads();

    // ---- t = LN(z)*pre_w + pre_b -> g_t ----
#pragma unroll
    for (int rr = 0; rr < 2; rr++) {
        int r = w * 2 + rr;
        float v[8]; float s = 0.f;
#pragma unroll
        for (int i = 0; i < 8; i++) { v[i] = zS[r][lane + 32 * i]; s += v[i]; }
        s = warp_sum(s);
        float mu = s * (1.f / DIMX);
        float sv = 0.f;
#pragma unroll
        for (int i = 0; i < 8; i++) { float d = v[i] - mu; sv += d * d; }
        sv = warp_sum(sv);
        float rs = rsqrtf(sv * (1.f / DIMX) + LN_EPS);
#pragma unroll
        for (int i = 0; i < 8; i++) {
            int c = lane + 32 * i;
            g_t[(size_t)(row0 + r) * DIMX + c] = (v[i] - mu) * rs * pre_w[c] + pre_b[c];
        }
    }
}

// =============================================================================
// Kernel C2: h1 = gelu(t@W1^T+b1); z2 = t + h1@W2^T + b2; out = LN(z2)
// One CTA = 16 rows, 256 threads.
// =============================================================================
__global__ __launch_bounds__(256) void kC2(
    const float* __restrict__ W1, const float* __restrict__ b1,
    const float* __restrict__ W2, const float* __restrict__ b2,
    const float* __restrict__ post_w, const float* __restrict__ post_b,
    float* __restrict__ out)
{
    __shared__ float h1S[16][512];   // 32 KB; first 16 KB reused as z2 buffer afterwards
    const int tid = threadIdx.x, lane = tid & 31, w = tid >> 5;
    const int row0 = blockIdx.x * 16;

    // ---- h1 = gelu(W1 t + b1): thread handles outputs tid and tid+256 ----
#pragma unroll
    for (int oi = 0; oi < 2; oi++) {
        int o = oi * 256 + tid;
        float acc[16];
#pragma unroll
        for (int r = 0; r < 16; r++) acc[r] = 0.f;
        const float4* wr = (const float4*)(W1 + (size_t)o * DIMX);
        for (int c4 = 0; c4 < 64; c4++) {
            float4 w4 = wr[c4];
#pragma unroll
            for (int r = 0; r < 16; r++) {
                float4 t4 = *((const float4*)(g_t + (size_t)(row0 + r) * DIMX) + c4);
                acc[r] = fmaf(t4.x, w4.x, acc[r]);
                acc[r] = fmaf(t4.y, w4.y, acc[r]);
                acc[r] = fmaf(t4.z, w4.z, acc[r]);
                acc[r] = fmaf(t4.w, w4.w, acc[r]);
            }
        }
        float bb = b1[o];
#pragma unroll
        for (int r = 0; r < 16; r++) {
            float zv = acc[r] + bb;
            h1S[r][o] = 0.5f * zv * (1.0f + erff(zv * 0.7071067811865475f));
        }
    }
    __syncthreads();

    // ---- h2 + residual, kept in registers ----
    float z2[16];
    {
        float acc[16];
#pragma unroll
        for (int r = 0; r < 16; r++) acc[r] = 0.f;
        const float4* wr = (const float4*)(W2 + (size_t)tid * 512);
        for (int c4 = 0; c4 < 128; c4++) {
            float4 w4 = wr[c4];
#pragma unroll
            for (int r = 0; r < 16; r++) {
                float4 hh = *(const float4*)&h1S[r][c4 * 4];
                acc[r] = fmaf(hh.x, w4.x, acc[r]);
                acc[r] = fmaf(hh.y, w4.y, acc[r]);
                acc[r] = fmaf(hh.z, w4.z, acc[r]);
                acc[r] = fmaf(hh.w, w4.w, acc[r]);
            }
        }
        float bb = b2[tid];
#pragma unroll
        for (int r = 0; r < 16; r++)
            z2[r] = g_t[(size_t)(row0 + r) * DIMX + tid] + acc[r] + bb;
    }
    __syncthreads();

    // ---- stash z2 into the (now free) h1S region for the row-wise LN ----
    float* z2S = &h1S[0][0];   // treated as [16][256]
#pragma unroll
    for (int r = 0; r < 16; r++) z2S[r * 256 + tid] = z2[r];
    __syncthreads();

    // ---- final LN -> out ----
#pragma unroll
    for (int rr = 0; rr < 2; rr++) {
        int r = w * 2 + rr;
        float v[8]; float s = 0.f;
#pragma unroll
        for (int i = 0; i < 8; i++) { v[i] = z2S[r * 256 + lane + 32 * i]; s += v[i]; }
        s = warp_sum(s);
        float mu = s * (1.f / DIMX);
        float sv = 0.f;
#pragma unroll
        for (int i = 0; i < 8; i++) { float d = v[i] - mu; sv += d * d; }
        sv = warp_sum(sv);
        float rs = rsqrtf(sv * (1.f / DIMX) + LN_EPS);
#pragma unroll
        for (int i = 0; i < 8; i++) {
            int c = lane + 32 * i;
            out[(size_t)(row0 + r) * DIMX + c] = (v[i] - mu) * rs * post_w[c] + post_b[c];
        }
    }
}

// =============================================================================
extern "C" void kernel_launch(void* const* d_in, const int* in_sizes, int n_in,
                              void* d_out, int out_size)
{
    const float* x      = (const float*)d_in[0];
    const float* y      = (const float*)d_in[1];
    const float* lnq_w  = (const float*)d_in[2];
    const float* lnq_b  = (const float*)d_in[3];
    const float* Wq     = (const float*)d_in[4];
    const float* bq     = (const float*)d_in[5];
    const float* lnk_w  = (const float*)d_in[6];
    const float* lnk_b  = (const float*)d_in[7];
    const float* Wk     = (const float*)d_in[8];
    const float* bk     = (const float*)d_in[9];
    const float* lnv_w  = (const float*)d_in[10];
    const float* lnv_b  = (const float*)d_in[11];
    const float* Wv     = (const float*)d_in[12];
    const float* bv     = (const float*)d_in[13];
    const float* Wp     = (const float*)d_in[14];
    const float* bp     = (const float*)d_in[15];
    const float* pre_w  = (const float*)d_in[16];
    const float* pre_b  = (const float*)d_in[17];
    const float* W1     = (const float*)d_in[18];
    const float* b1     = (const float*)d_in[19];
    const float* W2     = (const float*)d_in[20];
    const float* b2     = (const float*)d_in[21];
    const float* post_w = (const float*)d_in[22];
    const float* post_b = (const float*)d_in[23];
    float* out = (float*)d_out;

    kA <<<BMROWS / 16, 256>>> (x, lnq_w, lnq_b, Wq, bq, Wk, bk);
    kB <<<BMROWS,      256>>> (y, lnk_w, lnk_b, lnv_w, lnv_b);
    kC1<<<BMROWS / 16, 256>>> (Wv, bv, Wp, bp, pre_w, pre_b);
    kC2<<<BMROWS / 16, 256>>> (W1, b1, W2, b2, post_w, post_b, out);
}

// round 3
// speedup vs baseline: 1.8371x; 1.8357x over previous
#include <cuda_runtime.h>
#include <math.h>

#define LN_EPS 1e-5f
#define ATT_SCALE 0.17677669529663687f

// ---------- scratch (device globals, zero-initialized, no allocation) ----------
__device__ float g_xn  [(size_t)8192 * 256];
__device__ float g_q   [(size_t)8192 * 256];
__device__ float g_qWH [(size_t)8 * 8192 * 256];   // [h][row][c]
__device__ float g_ybarH[(size_t)8 * 8192 * 256];  // [h][row][c]
__device__ float g_a   [(size_t)8192 * 256];
__device__ float g_t   [(size_t)8192 * 256];
__device__ float g_h1  [(size_t)8192 * 512];
__device__ float g_zero[256];

#define FMA2(acc, a, b) asm("fma.rn.f32x2 %0, %1, %2, %0;" : "+l"(acc) : "l"(a), "l"(b))

__device__ __forceinline__ unsigned long long dup2(float a) {
    unsigned long long r; asm("mov.b64 %0, {%1, %1};" : "=l"(r) : "f"(a)); return r;
}
__device__ __forceinline__ float2 u2f(unsigned long long u) {
    float2 f; f.x = __uint_as_float((unsigned)u); f.y = __uint_as_float((unsigned)(u >> 32)); return f;
}
__device__ __forceinline__ float warp_sum(float v) {
#pragma unroll
    for (int o = 16; o; o >>= 1) v += __shfl_xor_sync(0xffffffffu, v, o);
    return v;
}

// =============================================================================
// kLNx: g_xn = LN(x)*w + b. Warp per row.
// =============================================================================
__global__ __launch_bounds__(256) void kLNx(
    const float* __restrict__ x, const float* __restrict__ w, const float* __restrict__ b)
{
    const int lane = threadIdx.x & 31, wrp = threadIdx.x >> 5;
    const int row = blockIdx.x * 8 + wrp;
    const float* xr = x + (size_t)row * 256;
    float4 v0 = *(const float4*)&xr[lane * 4];
    float4 v1 = *(const float4*)&xr[128 + lane * 4];
    float s = v0.x + v0.y + v0.z + v0.w + v1.x + v1.y + v1.z + v1.w;
    s = warp_sum(s);
    float mu = s * (1.f / 256.f), d, sq = 0.f;
    d = v0.x - mu; sq += d * d; d = v0.y - mu; sq += d * d;
    d = v0.z - mu; sq += d * d; d = v0.w - mu; sq += d * d;
    d = v1.x - mu; sq += d * d; d = v1.y - mu; sq += d * d;
    d = v1.z - mu; sq += d * d; d = v1.w - mu; sq += d * d;
    sq = warp_sum(sq);
    float rs = rsqrtf(sq * (1.f / 256.f) + LN_EPS);
    float4 w0 = *(const float4*)&w[lane * 4], w1 = *(const float4*)&w[128 + lane * 4];
    float4 b0 = *(const float4*)&b[lane * 4], b1 = *(const float4*)&b[128 + lane * 4];
    float4 o0, o1;
    o0.x = (v0.x - mu) * rs * w0.x + b0.x; o0.y = (v0.y - mu) * rs * w0.y + b0.y;
    o0.z = (v0.z - mu) * rs * w0.z + b0.z; o0.w = (v0.w - mu) * rs * w0.w + b0.w;
    o1.x = (v1.x - mu) * rs * w1.x + b1.x; o1.y = (v1.y - mu) * rs * w1.y + b1.y;
    o1.z = (v1.z - mu) * rs * w1.z + b1.z; o1.w = (v1.w - mu) * rs * w1.w + b1.w;
    float* orow = g_xn + (size_t)row * 256;
    *(float4*)&orow[lane * 4] = o0; *(float4*)&orow[128 + lane * 4] = o1;
}

// =============================================================================
// gemm256: C[64 x 256 tile] = A @ op(W) + bias, EPI: 0 bias, 1 gelu, 2 LN, 3 res+LN
// WTRANS: W is [256n][K] (read W[n][k]); else W is [K][256n].
// =============================================================================
template<int EPI, bool WTRANS>
__global__ __launch_bounds__(256, 2) void gemm256(
    const float* __restrict__ A, int lda, int strideA,
    const float* __restrict__ W, int ldw, int strideW, int kin,
    const float* __restrict__ bias, int strideB,
    float* __restrict__ C, int ldc, int strideC,
    const float* __restrict__ lnw, const float* __restrict__ lnb,
    const float* __restrict__ res, int ldres)
{
    __shared__ __align__(16) float As[16][68];
    __shared__ __align__(16) float Ws[16][260];
    const int tid = threadIdx.x, lane = tid & 31, wrp = tid >> 5;
    const int row0 = blockIdx.x * 64;
    A += (size_t)blockIdx.y * strideA;
    W += (size_t)blockIdx.y * strideW;
    C += (size_t)blockIdx.y * strideC;
    bias += (size_t)blockIdx.y * strideB;

    unsigned long long acc[8][4];
#pragma unroll
    for (int r = 0; r < 8; r++) { acc[r][0] = 0; acc[r][1] = 0; acc[r][2] = 0; acc[r][3] = 0; }

    const int am = tid >> 2, akq = (tid & 3) * 4;   // A & WTRANS staging
    const int kr = tid >> 4, nq = (tid & 15) * 16;  // WTRANS=0 staging
    float4 av, wv[4];

    av = *(const float4*)&A[(size_t)(row0 + am) * lda + akq];
    if (WTRANS) {
#pragma unroll
        for (int oo = 0; oo < 4; oo++)
            wv[oo] = *(const float4*)&W[(size_t)(oo * 64 + am) * ldw + akq];
    } else {
#pragma unroll
        for (int q = 0; q < 4; q++)
            wv[q] = *(const float4*)&W[(size_t)kr * ldw + nq + q * 4];
    }

    for (int kc = 0; kc < kin; kc += 16) {
        { float ae[4]; *(float4*)ae = av;
#pragma unroll
          for (int j = 0; j < 4; j++) As[akq + j][am] = ae[j]; }
        if (WTRANS) {
#pragma unroll
            for (int oo = 0; oo < 4; oo++) {
                float we[4]; *(float4*)we = wv[oo];
#pragma unroll
                for (int j = 0; j < 4; j++) Ws[akq + j][oo * 64 + am] = we[j];
            }
        } else {
#pragma unroll
            for (int q = 0; q < 4; q++) *(float4*)&Ws[kr][nq + q * 4] = wv[q];
        }
        __syncthreads();

        if (kc + 16 < kin) {
            av = *(const float4*)&A[(size_t)(row0 + am) * lda + kc + 16 + akq];
            if (WTRANS) {
#pragma unroll
                for (int oo = 0; oo < 4; oo++)
                    wv[oo] = *(const float4*)&W[(size_t)(oo * 64 + am) * ldw + kc + 16 + akq];
            } else {
#pragma unroll
                for (int q = 0; q < 4; q++)
                    wv[q] = *(const float4*)&W[(size_t)(kc + 16 + kr) * ldw + nq + q * 4];
            }
        }

#pragma unroll
        for (int k = 0; k < 16; k++) {
            ulonglong2 w0 = *(const ulonglong2*)&Ws[k][lane * 4];
            ulonglong2 w1 = *(const ulonglong2*)&Ws[k][128 + lane * 4];
            float4 aA = *(const float4*)&As[k][wrp * 8];
            float4 aB = *(const float4*)&As[k][wrp * 8 + 4];
            float ar[8] = {aA.x, aA.y, aA.z, aA.w, aB.x, aB.y, aB.z, aB.w};
#pragma unroll
            for (int r = 0; r < 8; r++) {
                unsigned long long a2 = dup2(ar[r]);
                FMA2(acc[r][0], a2, w0.x); FMA2(acc[r][1], a2, w0.y);
                FMA2(acc[r][2], a2, w1.x); FMA2(acc[r][3], a2, w1.y);
            }
        }
        __syncthreads();
    }

    const int cA = lane * 4, cB = 128 + lane * 4;
    float4 bA = *(const float4*)&bias[cA];
    float4 bB = *(const float4*)&bias[cB];
    float4 lwA, lwB, lbA, lbB;
    if (EPI >= 2) {
        lwA = *(const float4*)&lnw[cA]; lwB = *(const float4*)&lnw[cB];
        lbA = *(const float4*)&lnb[cA]; lbB = *(const float4*)&lnb[cB];
    }
#pragma unroll
    for (int r = 0; r < 8; r++) {
        const int row = row0 + wrp * 8 + r;
        float2 p0 = u2f(acc[r][0]), p1 = u2f(acc[r][1]);
        float2 p2 = u2f(acc[r][2]), p3 = u2f(acc[r][3]);
        float v[8];
        v[0] = p0.x + bA.x; v[1] = p0.y + bA.y; v[2] = p1.x + bA.z; v[3] = p1.y + bA.w;
        v[4] = p2.x + bB.x; v[5] = p2.y + bB.y; v[6] = p3.x + bB.z; v[7] = p3.y + bB.w;
        if (EPI == 1) {
#pragma unroll
            for (int i = 0; i < 8; i++)
                v[i] = 0.5f * v[i] * (1.0f + erff(v[i] * 0.70710678118654752f));
        }
        if (EPI == 3) {
            const float* rr = res + (size_t)row * ldres;
            float4 r0 = *(const float4*)&rr[cA], r1 = *(const float4*)&rr[cB];
            v[0] += r0.x; v[1] += r0.y; v[2] += r0.z; v[3] += r0.w;
            v[4] += r1.x; v[5] += r1.y; v[6] += r1.z; v[7] += r1.w;
        }
        if (EPI >= 2) {
            float s = v[0]+v[1]+v[2]+v[3]+v[4]+v[5]+v[6]+v[7];
            s = warp_sum(s);
            float mu = s * (1.f / 256.f), sq = 0.f;
#pragma unroll
            for (int i = 0; i < 8; i++) { float d = v[i] - mu; sq += d * d; }
            sq = warp_sum(sq);
            float rs = rsqrtf(sq * (1.f / 256.f) + LN_EPS);
            v[0] = (v[0]-mu)*rs*lwA.x+lbA.x; v[1] = (v[1]-mu)*rs*lwA.y+lbA.y;
            v[2] = (v[2]-mu)*rs*lwA.z+lbA.z; v[3] = (v[3]-mu)*rs*lwA.w+lbA.w;
            v[4] = (v[4]-mu)*rs*lwB.x+lbB.x; v[5] = (v[5]-mu)*rs*lwB.y+lbB.y;
            v[6] = (v[6]-mu)*rs*lwB.z+lbB.z; v[7] = (v[7]-mu)*rs*lwB.w+lbB.w;
        }
        float4 o0 = {v[0], v[1], v[2], v[3]}, o1 = {v[4], v[5], v[6], v[7]};
        float* crow = C + (size_t)row * ldc;
        *(float4*)&crow[cA] = o0; *(float4*)&crow[cB] = o1;
    }
}

// =============================================================================
// kB: per (b,m) row: LN(y), logits via qWH, softmax over N=32, ybar -> g_ybarH.
// =============================================================================
__global__ __launch_bounds__(256) void kB(
    const float* __restrict__ y,
    const float* __restrict__ lnk_w, const float* __restrict__ lnk_b,
    const float* __restrict__ lnv_w, const float* __restrict__ lnv_b,
    const float* __restrict__ bk)
{
    __shared__ __align__(16) float ysn[32][260];
    __shared__ __align__(16) float qWk[8][260];
    __shared__ float la[8][33], attn[8][33], qb2[8];
    const int tid = threadIdx.x, lane = tid & 31, w = tid >> 5;
    const int bm = blockIdx.x;
    const float4* ybase = (const float4*)(y + (size_t)bm * 8192);

#pragma unroll
    for (int j = 0; j < 8; j++) {
        int fi = j * 256 + tid, n = fi >> 6, c4 = fi & 63;
        *(float4*)&ysn[n][c4 * 4] = ybase[fi];
    }
    { // qkb per head (warp w = head w)
        float qv = g_q[(size_t)bm * 256 + w * 32 + lane] * bk[w * 32 + lane];
        qv = warp_sum(qv);
        if (lane == 0) qb2[w] = qv;
    }
    __syncthreads();

#pragma unroll
    for (int rr = 0; rr < 4; rr++) {  // LN rows (no affine; folded into qWk/ybar)
        int n = w * 4 + rr;
        float v[8]; float s = 0.f;
#pragma unroll
        for (int i = 0; i < 8; i++) { v[i] = ysn[n][lane + 32 * i]; s += v[i]; }
        s = warp_sum(s);
        float mu = s * (1.f / 256.f), sq = 0.f;
#pragma unroll
        for (int i = 0; i < 8; i++) { float d = v[i] - mu; sq += d * d; }
        sq = warp_sum(sq);
        float rs = rsqrtf(sq * (1.f / 256.f) + LN_EPS);
#pragma unroll
        for (int i = 0; i < 8; i++) ysn[n][lane + 32 * i] = (v[i] - mu) * rs;
    }
    {   // fold lnk affine into qW
        float lw = lnk_w[tid], lb = lnk_b[tid];
#pragma unroll
        for (int h = 0; h < 8; h++) {
            float qv = g_qWH[((size_t)h * 8192 + bm) * 256 + tid];
            qWk[h][tid] = qv * lw;
            float bp = warp_sum(qv * lb);
            if (lane == 0) atomicAdd(&qb2[h], bp);
        }
    }
    __syncthreads();

    {   // logits: thread -> (n, h)
        int n = tid >> 3, h = tid & 7;
        unsigned long long acc = 0;
        for (int c4 = 0; c4 < 64; c4++) {
            ulonglong2 a2 = *(const ulonglong2*)&ysn[n][c4 * 4];
            ulonglong2 b2 = *(const ulonglong2*)&qWk[h][c4 * 4];
            FMA2(acc, a2.x, b2.x); FMA2(acc, a2.y, b2.y);
        }
        float2 p = u2f(acc);
        la[h][n] = (p.x + p.y + qb2[h]) * ATT_SCALE;
    }
    __syncthreads();
    {   // softmax per head (warp = head)
        float v = la[w][lane], mx = v;
#pragma unroll
        for (int o = 16; o; o >>= 1) mx = fmaxf(mx, __shfl_xor_sync(0xffffffffu, mx, o));
        float e = __expf(v - mx);
        float s = warp_sum(e);
        attn[w][lane] = e / s;
    }
    __syncthreads();
    {   // ybar: thread -> (4 heads, col pair)
        int cp = tid & 127, hbase = (tid >> 7) * 4;
        float lvw0 = lnv_w[cp * 2], lvw1 = lnv_w[cp * 2 + 1];
        float lvb0 = lnv_b[cp * 2], lvb1 = lnv_b[cp * 2 + 1];
#pragma unroll
        for (int hh = 0; hh < 4; hh++) {
            int h = hbase + hh;
            unsigned long long acc = 0;
#pragma unroll
            for (int n = 0; n < 32; n++) {
                unsigned long long y2 = *(const unsigned long long*)&ysn[n][cp * 2];
                FMA2(acc, dup2(attn[h][n]), y2);
            }
            float2 p = u2f(acc);
            float2 o = {p.x * lvw0 + lvb0, p.y * lvw1 + lvb1};
            *(float2*)&g_ybarH[((size_t)h * 8192 + bm) * 256 + cp * 2] = o;
        }
    }
}

// =============================================================================
// aK: per head: a[:, h*32+d] = ybarH[h] @ Wv_h^T + bv. 256 rows x 32 cols per CTA.
// =============================================================================
__global__ __launch_bounds__(256, 2) void aK(
    const float* __restrict__ Wv, const float* __restrict__ bv)
{
    __shared__ __align__(16) float WsT[256][33];
    __shared__ __align__(16) float AsT[16][68];
    const int tid = threadIdx.x, lane = tid & 31, wrp = tid >> 5;
    const int row0 = blockIdx.x * 64;
    const int h = blockIdx.y;
    const float* A = g_ybarH + (size_t)h * 8192 * 256;

    {   // stage Wv_h transposed: WsT[c][d]
        int d = tid >> 3, c8 = (tid & 7) * 4;
#pragma unroll
        for (int j = 0; j < 8; j++) {
            int c = c8 + j * 32;
            float4 v = *(const float4*)&Wv[(size_t)(h * 32 + d) * 256 + c];
            WsT[c][d] = v.x; WsT[c + 1][d] = v.y; WsT[c + 2][d] = v.z; WsT[c + 3][d] = v.w;
        }
    }
    unsigned long long acc[4] = {0, 0, 0, 0};
    const int am = tid >> 2, akq = (tid & 3) * 4;
    float4 av = *(const float4*)&A[(size_t)(row0 + am) * 256 + akq];
    __syncthreads();

    for (int kc = 0; kc < 256; kc += 16) {
        { float ae[4]; *(float4*)ae = av;
#pragma unroll
          for (int j = 0; j < 4; j++) AsT[akq + j][am] = ae[j]; }
        __syncthreads();
        if (kc + 16 < 256)
            av = *(const float4*)&A[(size_t)(row0 + am) * 256 + kc + 16 + akq];
#pragma unroll
        for (int k = 0; k < 16; k++) {
            unsigned long long wd = dup2(WsT[kc + k][lane]);
            ulonglong2 a01 = *(const ulonglong2*)&AsT[k][wrp * 8];
            ulonglong2 a23 = *(const ulonglong2*)&AsT[k][wrp * 8 + 4];
            FMA2(acc[0], a01.x, wd); FMA2(acc[1], a01.y, wd);
            FMA2(acc[2], a23.x, wd); FMA2(acc[3], a23.y, wd);
        }
        __syncthreads();
    }
    float bvv = bv[h * 32 + lane];
#pragma unroll
    for (int i = 0; i < 4; i++) {
        float2 p = u2f(acc[i]);
        int row = row0 + wrp * 8 + 2 * i;
        g_a[(size_t)row * 256 + h * 32 + lane] = p.x + bvv;
        g_a[(size_t)(row + 1) * 256 + h * 32 + lane] = p.y + bvv;
    }
}

// =============================================================================
extern "C" void kernel_launch(void* const* d_in, const int* in_sizes, int n_in,
                              void* d_out, int out_size)
{
    const float* x      = (const float*)d_in[0];
    const float* y      = (const float*)d_in[1];
    const float* lnq_w  = (const float*)d_in[2];
    const float* lnq_b  = (const float*)d_in[3];
    const float* Wq     = (const float*)d_in[4];
    const float* bq     = (const float*)d_in[5];
    const float* lnk_w  = (const float*)d_in[6];
    const float* lnk_b  = (const float*)d_in[7];
    const float* Wk     = (const float*)d_in[8];
    const float* bk     = (const float*)d_in[9];
    const float* lnv_w  = (const float*)d_in[10];
    const float* lnv_b  = (const float*)d_in[11];
    const float* Wv     = (const float*)d_in[12];
    const float* bv     = (const float*)d_in[13];
    const float* Wp     = (const float*)d_in[14];
    const float* bp     = (const float*)d_in[15];
    const float* pre_w  = (const float*)d_in[16];
    const float* pre_b  = (const float*)d_in[17];
    const float* W1     = (const float*)d_in[18];
    const float* b1     = (const float*)d_in[19];
    const float* W2     = (const float*)d_in[20];
    const float* b2     = (const float*)d_in[21];
    const float* post_w = (const float*)d_in[22];
    const float* post_b = (const float*)d_in[23];
    float* out = (float*)d_out;

    float* zg = nullptr; cudaGetSymbolAddress((void**)&zg, g_zero);
    float* xn = nullptr; cudaGetSymbolAddress((void**)&xn, g_xn);
    float* q  = nullptr; cudaGetSymbolAddress((void**)&q,  g_q);
    float* qWH= nullptr; cudaGetSymbolAddress((void**)&qWH,g_qWH);
    float* a  = nullptr; cudaGetSymbolAddress((void**)&a,  g_a);
    float* t  = nullptr; cudaGetSymbolAddress((void**)&t,  g_t);
    float* h1 = nullptr; cudaGetSymbolAddress((void**)&h1, g_h1);

    kLNx<<<1024, 256>>>(x, lnq_w, lnq_b);
    // q = LN(x) @ Wq^T + bq
    gemm256<0, true ><<<dim3(128, 1), 256>>>(xn, 256, 0, Wq, 256, 0, 256, bq, 0,
                                             q, 256, 0, nullptr, nullptr, nullptr, 0);
    // qWH[h] = q[:, h*32:+32] @ Wk[h*32:+32, :]
    gemm256<0, false><<<dim3(128, 8), 256>>>(q, 256, 32, Wk, 256, 32 * 256, 32, zg, 0,
                                             qWH, 256, 8192 * 256, nullptr, nullptr, nullptr, 0);
    kB<<<8192, 256>>>(y, lnk_w, lnk_b, lnv_w, lnv_b, bk);
    aK<<<dim3(128, 8), 256>>>(Wv, bv);
    // t = LN(a @ Wp^T + bp)
    gemm256<2, true ><<<dim3(128, 1), 256>>>(a, 256, 0, Wp, 256, 0, 256, bp, 0,
                                             t, 256, 0, pre_w, pre_b, nullptr, 0);
    // h1 = gelu(t @ W1^T + b1)
    gemm256<1, true ><<<dim3(128, 2), 256>>>(t, 256, 0, W1, 256, 256 * 256, 256, b1, 256,
                                             h1, 512, 256, nullptr, nullptr, nullptr, 0);
    // out = LN(t + h1 @ W2^T + b2)
    gemm256<3, true ><<<dim3(128, 1), 256>>>(h1, 512, 0, W2, 512, 0, 512, b2, 0,
                                             out, 256, 0, post_w, post_b, t, 256);
}